// round 12
// baseline (speedup 1.0000x reference)
#include <cuda.h>
#include <cuda_runtime.h>

#define Nn 16
#define Cc 64
#define Hh 256
#define Ww 256
#define HW 65536
#define NHW 1048576

// ---------------- scratch ----------------
__device__ float g_h[NHW];          // conv1 output (1 channel)
__device__ float g_fz[NHW];         // fuzzify output
__device__ float g_part1[256 * 2];  // K1 partials (sum, sumsq) per tile
__device__ float g_part2[512 * 54]; // K3' partials (v[9], M[45])
__device__ float g_Wf[64 * 10];     // fused conv2 weights (9) + bias (1)
__device__ int   g_ctr;             // K1 dynamic tile counter (memset per launch)

// ---------------- helpers ----------------
__device__ __forceinline__ unsigned smem_u32(const void* p) {
    unsigned r;
    asm("{ .reg .u64 t; cvta.to.shared.u64 t, %1; cvt.u32.u64 %0, t; }" : "=r"(r) : "l"(p));
    return r;
}
typedef unsigned long long u64t;
union F2U { float2 f2; u64t u; };
__device__ __forceinline__ u64t pk2(float lo, float hi) {
    u64t r;
    asm("mov.b64 %0, {%1, %2};" : "=l"(r) : "f"(lo), "f"(hi));
    return r;
}
__device__ __forceinline__ void fma2(u64t& d, u64t a, u64t b) {
    asm("fma.rn.f32x2 %0, %1, %2, %0;" : "+l"(d) : "l"(a), "l"(b));
}
__device__ __forceinline__ void upk2(float& lo, float& hi, u64t v) {
    asm("mov.b64 {%0, %1}, %2;" : "=f"(lo), "=f"(hi) : "l"(v));
}
// ---- mbarrier / TMA ----
__device__ __forceinline__ void mbar_init(unsigned a, unsigned cnt) {
    asm volatile("mbarrier.init.shared.b64 [%0], %1;" :: "r"(a), "r"(cnt) : "memory");
}
__device__ __forceinline__ void mbar_expect_tx(unsigned a, unsigned bytes) {
    asm volatile("mbarrier.arrive.expect_tx.shared.b64 _, [%0], %1;" :: "r"(a), "r"(bytes) : "memory");
}
__device__ __forceinline__ void mbar_arrive(unsigned a) {
    asm volatile("mbarrier.arrive.shared.b64 _, [%0];" :: "r"(a) : "memory");
}
__device__ __forceinline__ void mbar_wait(unsigned a, unsigned phase) {
    asm volatile(
        "{\n\t.reg .pred P;\n\t"
        "WL_%=:\n\t"
        "mbarrier.try_wait.parity.acquire.cta.shared::cta.b64 P, [%0], %1, 0x989680;\n\t"
        "@P bra.uni WD_%=;\n\t"
        "bra.uni WL_%=;\n\t"
        "WD_%=:\n\t}"
        :: "r"(a), "r"(phase) : "memory");
}
__device__ __forceinline__ void tma3d(unsigned dst, const CUtensorMap* map,
                                      int cx, int cy, int cz, unsigned mbar) {
    asm volatile(
        "cp.async.bulk.tensor.3d.shared::cta.global.tile.mbarrier::complete_tx::bytes "
        "[%0], [%1, {%2, %3, %4}], [%5];"
        :: "r"(dst), "l"(map), "r"(cx), "r"(cy), "r"(cz), "r"(mbar) : "memory");
}

// ================= K1: persistent conv1 via TMA ring + dynamic tile scheduler ===
// grid 296 (2 blocks/SM, all resident), 288 threads: 8 consumer warps + 1 producer.
// Producer pulls tiles (n, rowgroup-of-16) from g_ctr; DEPTH-5 ring runs
// continuously across tiles. Tile headers ride through smem under the full-
// barrier release/acquire chain; sentinel -1 terminates.
#define DEPTH1 5
#define TILE_F (18 * 256)           // floats per tile
#define TILE_B (TILE_F * 4)         // 18432 bytes
#define NTILES 256

__device__ __forceinline__ void k1_compute(const float* tilef, const u64t* swp,
                                           int c, int tx, int ty, u64t acc[8]) {
    u64t wp[9];
    #pragma unroll
    for (int j = 0; j < 9; ++j) wp[j] = swp[c * 9 + j];
    #pragma unroll
    for (int rr = 0; rr < 10; ++rr) {
        const float* row = tilef + (ty * 8 + rr) * 256;
        float vm = (tx > 0)   ? row[2 * tx - 1] : 0.f;
        F2U v2; v2.u = *(const u64t*)&row[2 * tx];
        float vq = (tx < 127) ? row[2 * tx + 2] : 0.f;
        u64t p0 = pk2(vm, v2.f2.x);
        u64t p1 = v2.u;
        u64t p2 = pk2(v2.f2.y, vq);
        #pragma unroll
        for (int kh = 0; kh < 3; ++kh) {
            int o = rr - kh;
            if (o >= 0 && o < 8) {
                fma2(acc[o], wp[kh * 3 + 0], p0);
                fma2(acc[o], wp[kh * 3 + 1], p1);
                fma2(acc[o], wp[kh * 3 + 2], p2);
            }
        }
    }
}

__global__ __launch_bounds__(288) void k1_conv1(const __grid_constant__ CUtensorMap tmap,
                                                const float* __restrict__ w1,
                                                const float* __restrict__ b1) {
    extern __shared__ __align__(128) float dynsm[];  // DEPTH1 * TILE_F floats
    __shared__ u64t swp[576];
    __shared__ float red[16];
    __shared__ int shdr[2];
    __shared__ __align__(8) u64t mbar[2 * DEPTH1];   // full[0..4], empty[0..4]

    const int tid = threadIdx.x;
    const unsigned mb0 = smem_u32(&mbar[0]);
    const unsigned tile0 = smem_u32(&dynsm[0]);

    for (int i = tid; i < 576; i += 288) { float w = w1[i]; swp[i] = pk2(w, w); }
    if (tid == 0) {
        #pragma unroll
        for (int s = 0; s < DEPTH1; ++s) {
            mbar_init(mb0 + s * 8, 1);                    // full: producer arrive (+tx)
            mbar_init(mb0 + (DEPTH1 + s) * 8, 8);         // empty: 8 consumer warps
        }
    }
    __syncthreads();

    if (tid >= 256) {
        // ----------------- producer warp (thread 256 acts) -----------------
        if (tid == 256) {
            int ps = 0, pph = 1, tseq = 0;   // parity-1: first DEPTH waits pass
            while (true) {
                int t = atomicAdd(&g_ctr, 1);
                if (t >= NTILES) {
                    mbar_wait(mb0 + (DEPTH1 + ps) * 8, pph);
                    shdr[tseq & 1] = -1;
                    mbar_arrive(mb0 + ps * 8);            // sentinel wake
                    break;
                }
                const int n = t >> 4, rg = t & 15;
                const int y0 = rg * 16 - 1;
                const int zb = n * Cc;
                for (int c = 0; c < 64; ++c) {
                    mbar_wait(mb0 + (DEPTH1 + ps) * 8, pph);
                    if (c == 0) shdr[tseq & 1] = t;
                    unsigned fb = mb0 + ps * 8;
                    mbar_expect_tx(fb, TILE_B);           // release covers shdr store
                    tma3d(tile0 + ps * TILE_B, &tmap, 0, y0, zb + c, fb);
                    if (++ps == DEPTH1) { ps = 0; pph ^= 1; }
                }
                ++tseq;
            }
        }
    } else {
        // ----------------- 8 consumer warps -----------------
        const int tx = tid & 127, ty = tid >> 7;
        const int lane = tid & 31, wid = tid >> 5;
        const float bb = __ldg(b1);

        u64t acc[8];
        #pragma unroll
        for (int i = 0; i < 8; ++i) acc[i] = 0ull;

        int cs = 0, cph = 0, chan = 0, tseq = 0, t = -1;
        while (true) {
            mbar_wait(mb0 + cs * 8, cph);
            if (chan == 0) {
                t = shdr[tseq & 1];
                if (t < 0) break;
            }
            k1_compute(dynsm + cs * TILE_F, swp, chan, tx, ty, acc);
            __syncwarp();
            if (lane == 0) mbar_arrive(mb0 + (DEPTH1 + cs) * 8);
            if (++cs == DEPTH1) { cs = 0; cph ^= 1; }
            if (++chan == 64) {
                // -------- epilogue for tile t (overlaps next tile's TMA) --------
                const int n = t >> 4, rg = t & 15;
                float s = 0.f, s2 = 0.f;
                size_t obase = (size_t)n * HW + (size_t)(rg * 16 + ty * 8) * Ww + 2 * tx;
                #pragma unroll
                for (int o = 0; o < 8; ++o) {
                    float v0, v1;
                    upk2(v0, v1, acc[o]);
                    v0 += bb; v1 += bb;
                    *(float2*)&g_h[obase + (size_t)o * Ww] = make_float2(v0, v1);
                    s  += v0 + v1;
                    s2 += v0 * v0 + v1 * v1;
                    acc[o] = 0ull;
                }
                #pragma unroll
                for (int off = 16; off; off >>= 1) {
                    s  += __shfl_down_sync(0xffffffffu, s,  off);
                    s2 += __shfl_down_sync(0xffffffffu, s2, off);
                }
                if (lane == 0) { red[wid] = s; red[8 + wid] = s2; }
                asm volatile("bar.sync 1, 256;" ::: "memory");
                if (tid == 0) {
                    float tt = 0.f, tt2 = 0.f;
                    #pragma unroll
                    for (int u = 0; u < 8; ++u) { tt += red[u]; tt2 += red[8 + u]; }
                    g_part1[t * 2 + 0] = tt;
                    g_part1[t * 2 + 1] = tt2;
                }
                chan = 0;
                ++tseq;
            }
        }
    }
}

// ================= K3': BN1 reduce (per block) + fuzzify + v/M Gram partials ====
// grid (32 rowgroups of 8, 16 n), 256 threads = one column each.
#define T3_ROWS 10
__global__ __launch_bounds__(256) void k3_fuzz(const float* __restrict__ g1,
                                               const float* __restrict__ be1,
                                               const float* __restrict__ lb,
                                               const float* __restrict__ ub) {
    __shared__ float sm[T3_ROWS][258];
    __shared__ float red54[8][54];
    __shared__ double dred[16];
    __shared__ float sAB[2];
    int tid = threadIdx.x;
    int rg = blockIdx.x, n = blockIdx.y;
    int wid = tid >> 5, lane = tid & 31;

    {
        float2 pa = *(const float2*)&g_part1[2 * tid];
        double s  = (double)pa.x;
        double s2 = (double)pa.y;
        #pragma unroll
        for (int off = 16; off; off >>= 1) {
            s  += __shfl_down_sync(0xffffffffu, s,  off);
            s2 += __shfl_down_sync(0xffffffffu, s2, off);
        }
        if (lane == 0) { dred[wid] = s; dred[8 + wid] = s2; }
    }
    for (int i = tid; i < T3_ROWS * 258; i += 256) (&sm[0][0])[i] = 0.f;
    __syncthreads();
    if (tid == 0) {
        double s = 0.0, s2 = 0.0;
        #pragma unroll
        for (int u = 0; u < 8; ++u) { s += dred[u]; s2 += dred[8 + u]; }
        double m   = s  / (double)NHW;
        double var = s2 / (double)NHW - m * m;
        double inv = 1.0 / sqrt(var + 1e-5);
        double A   = (double)g1[0] * inv;
        sAB[0] = (float)A;
        sAB[1] = (float)((double)be1[0] - m * A);
    }
    __syncthreads();
    const float A = sAB[0], B = sAB[1];

    float Ls[4], Us[4];
    #pragma unroll
    for (int f = 0; f < 4; ++f) { Ls[f] = __ldg(lb + f); Us[f] = __ldg(ub + f); }

    const float* hbase = g_h  + (size_t)n * HW;
    float*       fbase = g_fz + (size_t)n * HW;
    #pragma unroll
    for (int r = 0; r < T3_ROWS; ++r) {
        int gr = rg * 8 - 1 + r;
        if (gr >= 0 && gr < Hh) {
            float xv = hbase[gr * Ww + tid] * A + B;
            float fz = 0.f;
            #pragma unroll
            for (int f = 0; f < 4; ++f) {
                float lbv = Ls[f], ubv = Us[f];
                float ld = xv - lbv, ud = ubv - xv;
                bool inr  = (ld > 0.f) && (ud > 0.f);
                bool outr = (ld < 0.f) || (ud < 0.f);
                float e1 = __expf(-0.5f * ld * ld);
                float a2 = inr ? ud : (ud + 2.f * ld);
                float e2 = __expf(-0.5f * a2 * a2);
                fz += (inr || outr) ? (e1 + e2) : 0.f;
                if (outr) xv = 2.f * lbv - xv;
            }
            sm[r][tid + 1] = fz;
            if (r >= 1 && r <= 8) fbase[gr * Ww + tid] = fz;
        }
    }
    __syncthreads();

    float v[9], M[45];
    #pragma unroll
    for (int i = 0; i < 9; ++i) v[i] = 0.f;
    #pragma unroll
    for (int i = 0; i < 45; ++i) M[i] = 0.f;

    float f0 = sm[0][tid], f1 = sm[0][tid + 1], f2 = sm[0][tid + 2];
    float f3 = sm[1][tid], f4 = sm[1][tid + 1], f5 = sm[1][tid + 2];
    #pragma unroll
    for (int o = 0; o < 8; ++o) {
        float f6 = sm[o + 2][tid], f7 = sm[o + 2][tid + 1], f8 = sm[o + 2][tid + 2];
        float f[9] = {f0, f1, f2, f3, f4, f5, f6, f7, f8};
        int k = 0;
        #pragma unroll
        for (int i = 0; i < 9; ++i) {
            v[i] += f[i];
            #pragma unroll
            for (int j = i; j < 9; ++j) M[k++] = fmaf(f[i], f[j], M[k]);
        }
        f0 = f3; f1 = f4; f2 = f5;
        f3 = f6; f4 = f7; f5 = f8;
    }

    #pragma unroll
    for (int q = 0; q < 54; ++q) {
        float t = (q < 9) ? v[q] : M[q - 9];
        #pragma unroll
        for (int off = 16; off; off >>= 1) t += __shfl_down_sync(0xffffffffu, t, off);
        if (lane == 0) red54[wid][q] = t;
    }
    __syncthreads();
    if (tid < 54) {
        float t = 0.f;
        #pragma unroll
        for (int u = 0; u < 8; ++u) t += red54[u][tid];
        g_part2[(n * 32 + rg) * 54 + tid] = t;
    }
}

// ================= K4b: reduce partials + per-channel BN2 fuse ==================
__global__ __launch_bounds__(512) void k4b_fuse(const float* __restrict__ w2,
                                                const float* __restrict__ b2,
                                                const float* __restrict__ g2,
                                                const float* __restrict__ be2) {
    __shared__ float redA[8][54];
    __shared__ double S[54];
    int tid = threadIdx.x;
    if (tid < 432) {
        int chunk = tid / 54, q = tid % 54;
        float t = 0.f;
        #pragma unroll 8
        for (int b = chunk * 64; b < chunk * 64 + 64; ++b)
            t += g_part2[b * 54 + q];
        redA[chunk][q] = t;
    }
    __syncthreads();
    if (tid < 54) {
        double t = 0.0;
        #pragma unroll
        for (int u = 0; u < 8; ++u) t += (double)redA[u][tid];
        S[tid] = t;
    }
    __syncthreads();
    if (tid < 64) {
        int c = tid;
        double w[9];
        #pragma unroll
        for (int j = 0; j < 9; ++j) w[j] = (double)w2[c * 9 + j];
        double bb = (double)b2[c];
        double dot = 0.0;
        #pragma unroll
        for (int j = 0; j < 9; ++j) dot += w[j] * S[j];
        double S2 = 0.0;
        int k = 9;
        #pragma unroll
        for (int i = 0; i < 9; ++i)
            #pragma unroll
            for (int j = i; j < 9; ++j) {
                double m = S[k++];
                S2 += (i == j) ? w[i] * w[i] * m : 2.0 * w[i] * w[j] * m;
            }
        double S1   = dot + bb * (double)NHW;
        double sq   = S2 + 2.0 * bb * dot + bb * bb * (double)NHW;
        double mean = S1 / (double)NHW;
        double var  = sq / (double)NHW - mean * mean;
        double inv  = 1.0 / sqrt(var + 1e-5);
        double Af   = (double)g2[c] * inv;
        double Bf   = (double)be2[c] - mean * Af;
        #pragma unroll
        for (int j = 0; j < 9; ++j) g_Wf[c * 10 + j] = (float)(w[j] * Af);
        g_Wf[c * 10 + 9] = (float)(bb * Af + Bf);
    }
}

// ================= K5: conv2 (1ch -> 64ch) + fused BN2, write output ============
__global__ __launch_bounds__(256) void k5_conv2(float* __restrict__ out) {
    __shared__ u64t swf[640];
    int tid = threadIdx.x;
    int rg = blockIdx.x, n = blockIdx.y;
    int c0 = blockIdx.z * 32;
    for (int i = tid; i < 640; i += 256) { float w = g_Wf[i]; swf[i] = pk2(w, w); }
    __syncthreads();

    int wt = tid & 63, ht = tid >> 6;
    int wq = wt * 4, gr0 = rg * 8 + ht * 2;
    const float* base = g_fz + (size_t)n * HW;

    u64t p[4][5];
    #pragma unroll
    for (int rr = 0; rr < 4; ++rr) {
        int gr = gr0 - 1 + rr;
        bool rok = (gr >= 0 && gr < Hh);
        float wv[6];
        #pragma unroll
        for (int cc = 0; cc < 6; ++cc) {
            int gc = wq - 1 + cc;
            bool ok = rok && (gc >= 0) && (gc < Ww);
            wv[cc] = ok ? __ldg(base + gr * Ww + gc) : 0.f;
        }
        #pragma unroll
        for (int cc = 0; cc < 5; ++cc) p[rr][cc] = pk2(wv[cc], wv[cc + 1]);
    }

    size_t obase = (size_t)n * Cc * HW + (size_t)gr0 * Ww + wq;
    for (int c = c0; c < c0 + 32; ++c) {
        u64t wp[9];
        #pragma unroll
        for (int j = 0; j < 9; ++j) wp[j] = swf[c * 10 + j];
        u64t bp = swf[c * 10 + 9];
        #pragma unroll
        for (int a = 0; a < 2; ++a) {
            u64t y01 = bp, y23 = bp;
            #pragma unroll
            for (int kh = 0; kh < 3; ++kh) {
                int row = a + kh;
                #pragma unroll
                for (int kw = 0; kw < 3; ++kw) {
                    fma2(y01, wp[kh * 3 + kw], p[row][kw]);
                    fma2(y23, wp[kh * 3 + kw], p[row][kw + 2]);
                }
            }
            float y0, y1, y2, y3;
            upk2(y0, y1, y01);
            upk2(y2, y3, y23);
            __stcs((float4*)(out + obase + (size_t)c * HW + (size_t)a * Ww),
                   make_float4(y0, y1, y2, y3));
        }
    }
}

// ================= launch =======================================================
typedef CUresult (*PFN_tmEnc)(CUtensorMap*, CUtensorMapDataType, cuuint32_t, void*,
                              const cuuint64_t*, const cuuint64_t*, const cuuint32_t*,
                              const cuuint32_t*, CUtensorMapInterleave, CUtensorMapSwizzle,
                              CUtensorMapL2promotion, CUtensorMapFloatOOBfill);

extern "C" void kernel_launch(void* const* d_in, const int* in_sizes, int n_in,
                              void* d_out, int out_size) {
    const float* x   = (const float*)d_in[0];
    const float* w1  = (const float*)d_in[1];
    const float* b1  = (const float*)d_in[2];
    const float* w2  = (const float*)d_in[3];
    const float* b2  = (const float*)d_in[4];
    const float* g1  = (const float*)d_in[5];
    const float* be1 = (const float*)d_in[6];
    const float* g2  = (const float*)d_in[7];
    const float* be2 = (const float*)d_in[8];
    const float* lb  = (const float*)d_in[9];
    const float* ub  = (const float*)d_in[10];
    float* out = (float*)d_out;

    static PFN_tmEnc tmEnc = nullptr;
    static void* ctr_addr = nullptr;
    if (!tmEnc) {
        void* fn = nullptr;
        cudaDriverEntryPointQueryResult st;
        cudaGetDriverEntryPoint("cuTensorMapEncodeTiled", &fn, cudaEnableDefault, &st);
        tmEnc = (PFN_tmEnc)fn;
        cudaGetSymbolAddress(&ctr_addr, g_ctr);
    }

    CUtensorMap tmap;
    {
        cuuint64_t dims[3]    = {256, 256, (cuuint64_t)(Cc * Nn)};
        cuuint64_t strides[2] = {256 * 4, (cuuint64_t)HW * 4};
        cuuint32_t box[3]     = {256, 18, 1};
        cuuint32_t es[3]      = {1, 1, 1};
        tmEnc(&tmap, CU_TENSOR_MAP_DATA_TYPE_FLOAT32, 3, (void*)x,
              dims, strides, box, es,
              CU_TENSOR_MAP_INTERLEAVE_NONE, CU_TENSOR_MAP_SWIZZLE_NONE,
              CU_TENSOR_MAP_L2_PROMOTION_L2_128B, CU_TENSOR_MAP_FLOAT_OOB_FILL_NONE);
    }

    static bool attr_set = false;
    const int k1_smem = DEPTH1 * TILE_B;   // 92160
    if (!attr_set) {
        cudaFuncSetAttribute(k1_conv1, cudaFuncAttributeMaxDynamicSharedMemorySize, k1_smem);
        attr_set = true;
    }

    cudaMemsetAsync(ctr_addr, 0, sizeof(int));
    k1_conv1<<<296, 288, k1_smem>>>(tmap, w1, b1);
    k3_fuzz<<<dim3(32, 16), 256>>>(g1, be1, lb, ub);
    k4b_fuse<<<1, 512>>>(w2, b2, g2, be2);
    k5_conv2<<<dim3(32, 16, 2), 256>>>(out);
}

// round 13
// speedup vs baseline: 1.0047x; 1.0047x over previous
#include <cuda.h>
#include <cuda_runtime.h>

#define Nn 16
#define Cc 64
#define Hh 256
#define Ww 256
#define HW 65536
#define NHW 1048576

// ---------------- scratch ----------------
__device__ float g_h[NHW];          // conv1 output (1 channel)
__device__ float g_fz[NHW];         // fuzzify output
__device__ float g_part1[256 * 2];  // K1 partials (sum, sumsq)
__device__ float g_part2[512 * 54]; // K3' partials (v[9], M[45])
__device__ float g_Wf[64 * 10];     // fused conv2 weights (9) + bias (1)

// ---------------- helpers ----------------
__device__ __forceinline__ unsigned smem_u32(const void* p) {
    unsigned r;
    asm("{ .reg .u64 t; cvta.to.shared.u64 t, %1; cvt.u32.u64 %0, t; }" : "=r"(r) : "l"(p));
    return r;
}
typedef unsigned long long u64t;
union F2U { float2 f2; u64t u; };
__device__ __forceinline__ u64t pk2(float lo, float hi) {
    u64t r;
    asm("mov.b64 %0, {%1, %2};" : "=l"(r) : "f"(lo), "f"(hi));
    return r;
}
__device__ __forceinline__ void fma2(u64t& d, u64t a, u64t b) {
    asm("fma.rn.f32x2 %0, %1, %2, %0;" : "+l"(d) : "l"(a), "l"(b));
}
__device__ __forceinline__ void upk2(float& lo, float& hi, u64t v) {
    asm("mov.b64 {%0, %1}, %2;" : "=f"(lo), "=f"(hi) : "l"(v));
}
// ---- mbarrier / TMA ----
__device__ __forceinline__ void mbar_init(unsigned a, unsigned cnt) {
    asm volatile("mbarrier.init.shared.b64 [%0], %1;" :: "r"(a), "r"(cnt) : "memory");
}
__device__ __forceinline__ void mbar_expect_tx(unsigned a, unsigned bytes) {
    asm volatile("mbarrier.arrive.expect_tx.shared.b64 _, [%0], %1;" :: "r"(a), "r"(bytes) : "memory");
}
__device__ __forceinline__ void mbar_arrive(unsigned a) {
    asm volatile("mbarrier.arrive.shared.b64 _, [%0];" :: "r"(a) : "memory");
}
__device__ __forceinline__ void mbar_wait(unsigned a, unsigned phase) {
    asm volatile(
        "{\n\t.reg .pred P;\n\t"
        "WL_%=:\n\t"
        "mbarrier.try_wait.parity.acquire.cta.shared::cta.b64 P, [%0], %1, 0x989680;\n\t"
        "@P bra.uni WD_%=;\n\t"
        "bra.uni WL_%=;\n\t"
        "WD_%=:\n\t}"
        :: "r"(a), "r"(phase) : "memory");
}
__device__ __forceinline__ void tma3d(unsigned dst, const CUtensorMap* map,
                                      int cx, int cy, int cz, unsigned mbar) {
    asm volatile(
        "cp.async.bulk.tensor.3d.shared::cta.global.tile.mbarrier::complete_tx::bytes "
        "[%0], [%1, {%2, %3, %4}], [%5];"
        :: "r"(dst), "l"(map), "r"(cx), "r"(cy), "r"(cz), "r"(mbar) : "memory");
}

// ================= K1: conv1 via TMA ring (64ch -> 1ch, 3x3 SAME) + BN1 partials
// grid (16 rowgroups of 16, 16 n), 288 threads: 8 consumer warps (128 col-pairs x
// 2 row-halves) + 1 dedicated TMA producer warp. DEPTH-5 ring of 18x256 tiles,
// each filled by TWO 9-row TMA loads (more independent request streams).
#define DEPTH1 5
#define TILE_F (18 * 256)           // floats per tile
#define TILE_B (TILE_F * 4)         // 18432 bytes
#define HALF_B (TILE_B / 2)         // 9216 bytes (9 rows)

__device__ __forceinline__ void k1_compute(const float* tilef, const u64t* swp,
                                           int c, int tx, int ty, u64t acc[8]) {
    u64t wp[9];
    #pragma unroll
    for (int j = 0; j < 9; ++j) wp[j] = swp[c * 9 + j];
    #pragma unroll
    for (int rr = 0; rr < 10; ++rr) {
        const float* row = tilef + (ty * 8 + rr) * 256;
        float vm = (tx > 0)   ? row[2 * tx - 1] : 0.f;
        F2U v2; v2.u = *(const u64t*)&row[2 * tx];
        float vq = (tx < 127) ? row[2 * tx + 2] : 0.f;
        u64t p0 = pk2(vm, v2.f2.x);
        u64t p1 = v2.u;
        u64t p2 = pk2(v2.f2.y, vq);
        #pragma unroll
        for (int kh = 0; kh < 3; ++kh) {
            int o = rr - kh;
            if (o >= 0 && o < 8) {
                fma2(acc[o], wp[kh * 3 + 0], p0);
                fma2(acc[o], wp[kh * 3 + 1], p1);
                fma2(acc[o], wp[kh * 3 + 2], p2);
            }
        }
    }
}

__global__ __launch_bounds__(288) void k1_conv1(const __grid_constant__ CUtensorMap tmap,
                                                const float* __restrict__ w1,
                                                const float* __restrict__ b1) {
    extern __shared__ __align__(128) float dynsm[];  // DEPTH1 * TILE_F floats
    __shared__ u64t swp[576];
    __shared__ float red[16];
    __shared__ __align__(8) u64t mbar[2 * DEPTH1];   // full[0..4], empty[0..4]

    const int tid = threadIdx.x;
    const int rg = blockIdx.x, n = blockIdx.y;
    const int tx = tid & 127, ty = (tid >> 7) & 1;
    const int lane = tid & 31;
    const unsigned mb0 = smem_u32(&mbar[0]);
    const unsigned tile0 = smem_u32(&dynsm[0]);

    for (int i = tid; i < 576; i += 288) { float w = w1[i]; swp[i] = pk2(w, w); }
    if (tid == 0) {
        #pragma unroll
        for (int s = 0; s < DEPTH1; ++s) {
            mbar_init(mb0 + s * 8, 1);                    // full: TMA complete_tx
            mbar_init(mb0 + (DEPTH1 + s) * 8, 8);         // empty: 8 consumer warps
        }
    }
    __syncthreads();

    const int zbase = n * Cc;
    const int y0 = rg * 16 - 1;

    if (tid >= 256) {
        // ---------- producer warp (only thread 256 acts) ----------
        if (tid == 256) {
            #pragma unroll
            for (int c = 0; c < DEPTH1 - 1; ++c) {        // prologue: ch 0..3
                unsigned fb = mb0 + c * 8;
                unsigned dst = tile0 + c * TILE_B;
                mbar_expect_tx(fb, TILE_B);
                tma3d(dst,          &tmap, 0, y0,     zbase + c, fb);
                tma3d(dst + HALF_B, &tmap, 0, y0 + 9, zbase + c, fb);
            }
            int ps = DEPTH1 - 1, pph = 1;
            for (int c = DEPTH1 - 1; c < 64; ++c) {       // ch 4..63
                unsigned eb = mb0 + (DEPTH1 + ps) * 8;
                unsigned fb = mb0 + ps * 8;
                unsigned dst = tile0 + ps * TILE_B;
                mbar_wait(eb, pph);
                mbar_expect_tx(fb, TILE_B);
                tma3d(dst,          &tmap, 0, y0,     zbase + c, fb);
                tma3d(dst + HALF_B, &tmap, 0, y0 + 9, zbase + c, fb);
                if (++ps == DEPTH1) { ps = 0; pph ^= 1; }
            }
        }
    } else {
        // ---------- 8 consumer warps ----------
        u64t acc[8];
        #pragma unroll
        for (int i = 0; i < 8; ++i) acc[i] = 0ull;

        int cs = 0, cph = 0;
        for (int c = 0; c < 64; ++c) {
            mbar_wait(mb0 + cs * 8, cph);
            k1_compute(dynsm + cs * TILE_F, swp, c, tx, ty, acc);
            __syncwarp();
            if (lane == 0) mbar_arrive(mb0 + (DEPTH1 + cs) * 8);
            if (++cs == DEPTH1) { cs = 0; cph ^= 1; }
        }

        const float bb = __ldg(b1);
        float s = 0.f, s2 = 0.f;
        size_t obase = (size_t)n * HW + (size_t)(rg * 16 + ty * 8) * Ww + 2 * tx;
        #pragma unroll
        for (int o = 0; o < 8; ++o) {
            float v0, v1;
            upk2(v0, v1, acc[o]);
            v0 += bb; v1 += bb;
            *(float2*)&g_h[obase + (size_t)o * Ww] = make_float2(v0, v1);
            s  += v0 + v1;
            s2 += v0 * v0 + v1 * v1;
        }
        #pragma unroll
        for (int off = 16; off; off >>= 1) {
            s  += __shfl_down_sync(0xffffffffu, s,  off);
            s2 += __shfl_down_sync(0xffffffffu, s2, off);
        }
        if (lane == 0) { red[tid >> 5] = s; red[8 + (tid >> 5)] = s2; }
    }
    __syncthreads();
    if (tid == 0) {
        float t = 0.f, t2 = 0.f;
        #pragma unroll
        for (int u = 0; u < 8; ++u) { t += red[u]; t2 += red[8 + u]; }
        int bid = n * 16 + rg;
        g_part1[bid * 2 + 0] = t;
        g_part1[bid * 2 + 1] = t2;
    }
}

// ================= K3': BN1 reduce (per block) + fuzzify + v/M Gram partials ====
// grid (32 rowgroups of 8, 16 n), 256 threads = one column each.
#define T3_ROWS 10
__global__ __launch_bounds__(256) void k3_fuzz(const float* __restrict__ g1,
                                               const float* __restrict__ be1,
                                               const float* __restrict__ lb,
                                               const float* __restrict__ ub) {
    __shared__ float sm[T3_ROWS][258];
    __shared__ float red54[8][54];
    __shared__ double dred[16];
    __shared__ float sAB[2];
    int tid = threadIdx.x;
    int rg = blockIdx.x, n = blockIdx.y;
    int wid = tid >> 5, lane = tid & 31;

    {
        float2 pa = *(const float2*)&g_part1[2 * tid];
        double s  = (double)pa.x;
        double s2 = (double)pa.y;
        #pragma unroll
        for (int off = 16; off; off >>= 1) {
            s  += __shfl_down_sync(0xffffffffu, s,  off);
            s2 += __shfl_down_sync(0xffffffffu, s2, off);
        }
        if (lane == 0) { dred[wid] = s; dred[8 + wid] = s2; }
    }
    for (int i = tid; i < T3_ROWS * 258; i += 256) (&sm[0][0])[i] = 0.f;
    __syncthreads();
    if (tid == 0) {
        double s = 0.0, s2 = 0.0;
        #pragma unroll
        for (int u = 0; u < 8; ++u) { s += dred[u]; s2 += dred[8 + u]; }
        double m   = s  / (double)NHW;
        double var = s2 / (double)NHW - m * m;
        double inv = 1.0 / sqrt(var + 1e-5);
        double A   = (double)g1[0] * inv;
        sAB[0] = (float)A;
        sAB[1] = (float)((double)be1[0] - m * A);
    }
    __syncthreads();
    const float A = sAB[0], B = sAB[1];

    float Ls[4], Us[4];
    #pragma unroll
    for (int f = 0; f < 4; ++f) { Ls[f] = __ldg(lb + f); Us[f] = __ldg(ub + f); }

    const float* hbase = g_h  + (size_t)n * HW;
    float*       fbase = g_fz + (size_t)n * HW;
    #pragma unroll
    for (int r = 0; r < T3_ROWS; ++r) {
        int gr = rg * 8 - 1 + r;
        if (gr >= 0 && gr < Hh) {
            float xv = hbase[gr * Ww + tid] * A + B;
            float fz = 0.f;
            #pragma unroll
            for (int f = 0; f < 4; ++f) {
                float lbv = Ls[f], ubv = Us[f];
                float ld = xv - lbv, ud = ubv - xv;
                bool inr  = (ld > 0.f) && (ud > 0.f);
                bool outr = (ld < 0.f) || (ud < 0.f);
                float e1 = __expf(-0.5f * ld * ld);
                float a2 = inr ? ud : (ud + 2.f * ld);
                float e2 = __expf(-0.5f * a2 * a2);
                fz += (inr || outr) ? (e1 + e2) : 0.f;
                if (outr) xv = 2.f * lbv - xv;
            }
            sm[r][tid + 1] = fz;
            if (r >= 1 && r <= 8) fbase[gr * Ww + tid] = fz;
        }
    }
    __syncthreads();

    float v[9], M[45];
    #pragma unroll
    for (int i = 0; i < 9; ++i) v[i] = 0.f;
    #pragma unroll
    for (int i = 0; i < 45; ++i) M[i] = 0.f;

    float f0 = sm[0][tid], f1 = sm[0][tid + 1], f2 = sm[0][tid + 2];
    float f3 = sm[1][tid], f4 = sm[1][tid + 1], f5 = sm[1][tid + 2];
    #pragma unroll
    for (int o = 0; o < 8; ++o) {
        float f6 = sm[o + 2][tid], f7 = sm[o + 2][tid + 1], f8 = sm[o + 2][tid + 2];
        float f[9] = {f0, f1, f2, f3, f4, f5, f6, f7, f8};
        int k = 0;
        #pragma unroll
        for (int i = 0; i < 9; ++i) {
            v[i] += f[i];
            #pragma unroll
            for (int j = i; j < 9; ++j) M[k++] = fmaf(f[i], f[j], M[k]);
        }
        f0 = f3; f1 = f4; f2 = f5;
        f3 = f6; f4 = f7; f5 = f8;
    }

    #pragma unroll
    for (int q = 0; q < 54; ++q) {
        float t = (q < 9) ? v[q] : M[q - 9];
        #pragma unroll
        for (int off = 16; off; off >>= 1) t += __shfl_down_sync(0xffffffffu, t, off);
        if (lane == 0) red54[wid][q] = t;
    }
    __syncthreads();
    if (tid < 54) {
        float t = 0.f;
        #pragma unroll
        for (int u = 0; u < 8; ++u) t += red54[u][tid];
        g_part2[(n * 32 + rg) * 54 + tid] = t;
    }
}

// ================= K4b: reduce partials + per-channel BN2 fuse ==================
__global__ __launch_bounds__(512) void k4b_fuse(const float* __restrict__ w2,
                                                const float* __restrict__ b2,
                                                const float* __restrict__ g2,
                                                const float* __restrict__ be2) {
    __shared__ float redA[8][54];
    __shared__ double S[54];
    int tid = threadIdx.x;
    if (tid < 432) {
        int chunk = tid / 54, q = tid % 54;
        float t = 0.f;
        #pragma unroll 8
        for (int b = chunk * 64; b < chunk * 64 + 64; ++b)
            t += g_part2[b * 54 + q];
        redA[chunk][q] = t;
    }
    __syncthreads();
    if (tid < 54) {
        double t = 0.0;
        #pragma unroll
        for (int u = 0; u < 8; ++u) t += (double)redA[u][tid];
        S[tid] = t;
    }
    __syncthreads();
    if (tid < 64) {
        int c = tid;
        double w[9];
        #pragma unroll
        for (int j = 0; j < 9; ++j) w[j] = (double)w2[c * 9 + j];
        double bb = (double)b2[c];
        double dot = 0.0;
        #pragma unroll
        for (int j = 0; j < 9; ++j) dot += w[j] * S[j];
        double S2 = 0.0;
        int k = 9;
        #pragma unroll
        for (int i = 0; i < 9; ++i)
            #pragma unroll
            for (int j = i; j < 9; ++j) {
                double m = S[k++];
                S2 += (i == j) ? w[i] * w[i] * m : 2.0 * w[i] * w[j] * m;
            }
        double S1   = dot + bb * (double)NHW;
        double sq   = S2 + 2.0 * bb * dot + bb * bb * (double)NHW;
        double mean = S1 / (double)NHW;
        double var  = sq / (double)NHW - mean * mean;
        double inv  = 1.0 / sqrt(var + 1e-5);
        double Af   = (double)g2[c] * inv;
        double Bf   = (double)be2[c] - mean * Af;
        #pragma unroll
        for (int j = 0; j < 9; ++j) g_Wf[c * 10 + j] = (float)(w[j] * Af);
        g_Wf[c * 10 + 9] = (float)(bb * Af + Bf);
    }
}

// ================= K5: conv2 (1ch -> 64ch) + fused BN2, write output ============
__global__ __launch_bounds__(256) void k5_conv2(float* __restrict__ out) {
    __shared__ u64t swf[640];
    int tid = threadIdx.x;
    int rg = blockIdx.x, n = blockIdx.y;
    int c0 = blockIdx.z * 32;
    for (int i = tid; i < 640; i += 256) { float w = g_Wf[i]; swf[i] = pk2(w, w); }
    __syncthreads();

    int wt = tid & 63, ht = tid >> 6;
    int wq = wt * 4, gr0 = rg * 8 + ht * 2;
    const float* base = g_fz + (size_t)n * HW;

    u64t p[4][5];
    #pragma unroll
    for (int rr = 0; rr < 4; ++rr) {
        int gr = gr0 - 1 + rr;
        bool rok = (gr >= 0 && gr < Hh);
        float wv[6];
        #pragma unroll
        for (int cc = 0; cc < 6; ++cc) {
            int gc = wq - 1 + cc;
            bool ok = rok && (gc >= 0) && (gc < Ww);
            wv[cc] = ok ? __ldg(base + gr * Ww + gc) : 0.f;
        }
        #pragma unroll
        for (int cc = 0; cc < 5; ++cc) p[rr][cc] = pk2(wv[cc], wv[cc + 1]);
    }

    size_t obase = (size_t)n * Cc * HW + (size_t)gr0 * Ww + wq;
    for (int c = c0; c < c0 + 32; ++c) {
        u64t wp[9];
        #pragma unroll
        for (int j = 0; j < 9; ++j) wp[j] = swf[c * 10 + j];
        u64t bp = swf[c * 10 + 9];
        #pragma unroll
        for (int a = 0; a < 2; ++a) {
            u64t y01 = bp, y23 = bp;
            #pragma unroll
            for (int kh = 0; kh < 3; ++kh) {
                int row = a + kh;
                #pragma unroll
                for (int kw = 0; kw < 3; ++kw) {
                    fma2(y01, wp[kh * 3 + kw], p[row][kw]);
                    fma2(y23, wp[kh * 3 + kw], p[row][kw + 2]);
                }
            }
            float y0, y1, y2, y3;
            upk2(y0, y1, y01);
            upk2(y2, y3, y23);
            __stcs((float4*)(out + obase + (size_t)c * HW + (size_t)a * Ww),
                   make_float4(y0, y1, y2, y3));
        }
    }
}

// ================= launch =======================================================
typedef CUresult (*PFN_tmEnc)(CUtensorMap*, CUtensorMapDataType, cuuint32_t, void*,
                              const cuuint64_t*, const cuuint64_t*, const cuuint32_t*,
                              const cuuint32_t*, CUtensorMapInterleave, CUtensorMapSwizzle,
                              CUtensorMapL2promotion, CUtensorMapFloatOOBfill);

extern "C" void kernel_launch(void* const* d_in, const int* in_sizes, int n_in,
                              void* d_out, int out_size) {
    const float* x   = (const float*)d_in[0];
    const float* w1  = (const float*)d_in[1];
    const float* b1  = (const float*)d_in[2];
    const float* w2  = (const float*)d_in[3];
    const float* b2  = (const float*)d_in[4];
    const float* g1  = (const float*)d_in[5];
    const float* be1 = (const float*)d_in[6];
    const float* g2  = (const float*)d_in[7];
    const float* be2 = (const float*)d_in[8];
    const float* lb  = (const float*)d_in[9];
    const float* ub  = (const float*)d_in[10];
    float* out = (float*)d_out;

    static PFN_tmEnc tmEnc = nullptr;
    if (!tmEnc) {
        void* fn = nullptr;
        cudaDriverEntryPointQueryResult st;
        cudaGetDriverEntryPoint("cuTensorMapEncodeTiled", &fn, cudaEnableDefault, &st);
        tmEnc = (PFN_tmEnc)fn;
    }

    CUtensorMap tmap;
    {
        cuuint64_t dims[3]    = {256, 256, (cuuint64_t)(Cc * Nn)};
        cuuint64_t strides[2] = {256 * 4, (cuuint64_t)HW * 4};
        cuuint32_t box[3]     = {256, 9, 1};     // 9-row half-boxes
        cuuint32_t es[3]      = {1, 1, 1};
        tmEnc(&tmap, CU_TENSOR_MAP_DATA_TYPE_FLOAT32, 3, (void*)x,
              dims, strides, box, es,
              CU_TENSOR_MAP_INTERLEAVE_NONE, CU_TENSOR_MAP_SWIZZLE_NONE,
              CU_TENSOR_MAP_L2_PROMOTION_L2_256B, CU_TENSOR_MAP_FLOAT_OOB_FILL_NONE);
    }

    static bool attr_set = false;
    const int k1_smem = DEPTH1 * TILE_B;   // 92160
    if (!attr_set) {
        cudaFuncSetAttribute(k1_conv1, cudaFuncAttributeMaxDynamicSharedMemorySize, k1_smem);
        attr_set = true;
    }

    k1_conv1<<<dim3(16, 16), 288, k1_smem>>>(tmap, w1, b1);
    k3_fuzz<<<dim3(32, 16), 256>>>(g1, be1, lb, ub);
    k4b_fuse<<<1, 512>>>(w2, b2, g2, be2);
    k5_conv2<<<dim3(32, 16, 2), 256>>>(out);
}

// round 14
// speedup vs baseline: 1.0173x; 1.0126x over previous
#include <cuda.h>
#include <cuda_runtime.h>

#define Nn 16
#define Cc 64
#define Hh 256
#define Ww 256
#define HW 65536
#define NHW 1048576

// ---------------- scratch ----------------
__device__ float g_h[NHW];          // conv1 output (1 channel)
__device__ float g_fz[NHW];         // fuzzify output
__device__ float g_part1[256 * 2];  // K1 partials (sum, sumsq)
__device__ float g_part2[512 * 54]; // K3' partials (v[9], M[45])
__device__ float g_Wf[64 * 10];     // fused conv2 weights (9) + bias (1)

// ---------------- helpers ----------------
__device__ __forceinline__ unsigned smem_u32(const void* p) {
    unsigned r;
    asm("{ .reg .u64 t; cvta.to.shared.u64 t, %1; cvt.u32.u64 %0, t; }" : "=r"(r) : "l"(p));
    return r;
}
typedef unsigned long long u64t;
union F2U { float2 f2; u64t u; };
__device__ __forceinline__ u64t pk2(float lo, float hi) {
    u64t r;
    asm("mov.b64 %0, {%1, %2};" : "=l"(r) : "f"(lo), "f"(hi));
    return r;
}
__device__ __forceinline__ void fma2(u64t& d, u64t a, u64t b) {
    asm("fma.rn.f32x2 %0, %1, %2, %0;" : "+l"(d) : "l"(a), "l"(b));
}
__device__ __forceinline__ void upk2(float& lo, float& hi, u64t v) {
    asm("mov.b64 {%0, %1}, %2;" : "=f"(lo), "=f"(hi) : "l"(v));
}
// ---- mbarrier / TMA ----
__device__ __forceinline__ void mbar_init(unsigned a, unsigned cnt) {
    asm volatile("mbarrier.init.shared.b64 [%0], %1;" :: "r"(a), "r"(cnt) : "memory");
}
__device__ __forceinline__ void mbar_expect_tx(unsigned a, unsigned bytes) {
    asm volatile("mbarrier.arrive.expect_tx.shared.b64 _, [%0], %1;" :: "r"(a), "r"(bytes) : "memory");
}
__device__ __forceinline__ void mbar_arrive(unsigned a) {
    asm volatile("mbarrier.arrive.shared.b64 _, [%0];" :: "r"(a) : "memory");
}
__device__ __forceinline__ void mbar_wait(unsigned a, unsigned phase) {
    asm volatile(
        "{\n\t.reg .pred P;\n\t"
        "WL_%=:\n\t"
        "mbarrier.try_wait.parity.acquire.cta.shared::cta.b64 P, [%0], %1, 0x989680;\n\t"
        "@P bra.uni WD_%=;\n\t"
        "bra.uni WL_%=;\n\t"
        "WD_%=:\n\t}"
        :: "r"(a), "r"(phase) : "memory");
}
__device__ __forceinline__ void tma3d(unsigned dst, const CUtensorMap* map,
                                      int cx, int cy, int cz, unsigned mbar) {
    asm volatile(
        "cp.async.bulk.tensor.3d.shared::cta.global.tile.mbarrier::complete_tx::bytes "
        "[%0], [%1, {%2, %3, %4}], [%5];"
        :: "r"(dst), "l"(map), "r"(cx), "r"(cy), "r"(cz), "r"(mbar) : "memory");
}

// ================= K1: conv1 via TMA ring (64ch -> 1ch, 3x3 SAME) + BN1 partials
// grid (16 rowgroups of 16, 16 n), 288 threads: 8 consumer warps (128 col-pairs x
// 2 row-halves) + 1 dedicated TMA producer warp. DEPTH-5 ring of 18x256 tiles.
// Halo-free inner loop: each thread accumulates own-pair terms + boundary
// accumulators bb, exchanged once through smem after the channel loop.
#define DEPTH1 5
#define TILE_F (18 * 256)           // floats per tile
#define TILE_B (TILE_F * 4)         // 18432 bytes

// weight table per channel/kh: [0]=(w1,w0) [1]=(w2,w1) [2]=(w2,w0)
__device__ __forceinline__ void k1_compute(const float* tilef, const u64t* swp,
                                           int c, int tx, int ty,
                                           u64t acc[8], u64t bb[8]) {
    u64t wp[9];
    #pragma unroll
    for (int j = 0; j < 9; ++j) wp[j] = swp[c * 9 + j];
    #pragma unroll
    for (int rr = 0; rr < 10; ++rr) {
        const float* row = tilef + (ty * 8 + rr) * 256;
        F2U v2; v2.u = *(const u64t*)&row[2 * tx];
        u64t pf0 = pk2(v2.f2.x, v2.f2.x);
        u64t pf1 = pk2(v2.f2.y, v2.f2.y);
        #pragma unroll
        for (int kh = 0; kh < 3; ++kh) {
            int o = rr - kh;
            if (o >= 0 && o < 8) {
                fma2(acc[o], wp[kh * 3 + 0], pf0);
                fma2(acc[o], wp[kh * 3 + 1], pf1);
                fma2(bb[o],  wp[kh * 3 + 2], v2.u);
            }
        }
    }
}

__global__ __launch_bounds__(288) void k1_conv1(const __grid_constant__ CUtensorMap tmap,
                                                const float* __restrict__ w1,
                                                const float* __restrict__ b1) {
    extern __shared__ __align__(128) float dynsm[];  // DEPTH1 * TILE_F floats
    __shared__ u64t swp[576];
    __shared__ float red[16];
    __shared__ __align__(8) u64t mbar[2 * DEPTH1];   // full[0..4], empty[0..4]

    const int tid = threadIdx.x;
    const int rg = blockIdx.x, n = blockIdx.y;
    const int tx = tid & 127, ty = (tid >> 7) & 1;
    const int lane = tid & 31;
    const unsigned mb0 = smem_u32(&mbar[0]);
    const unsigned tile0 = smem_u32(&dynsm[0]);

    // weight table: per (c,kh): (w1,w0), (w2,w1), (w2,w0)
    for (int i = tid; i < 576; i += 288) {
        int base = (i / 3) * 3;                 // c*9 + kh*3
        int j = i % 3;
        float wa = w1[base + ((j == 0) ? 1 : 2)];          // w1 / w2 / w2
        float wbv = w1[base + ((j == 1) ? 1 : 0)];         // w0 / w1 / w0
        swp[i] = pk2(wa, wbv);
    }
    if (tid == 0) {
        #pragma unroll
        for (int s = 0; s < DEPTH1; ++s) {
            mbar_init(mb0 + s * 8, 1);                    // full: TMA complete_tx
            mbar_init(mb0 + (DEPTH1 + s) * 8, 8);         // empty: 8 consumer warps
        }
    }
    __syncthreads();

    const int zbase = n * Cc;
    const int y0 = rg * 16 - 1;

    if (tid >= 256) {
        // ---------- producer warp (only thread 256 acts) ----------
        if (tid == 256) {
            #pragma unroll
            for (int c = 0; c < DEPTH1 - 1; ++c) {        // prologue: ch 0..3
                unsigned fb = mb0 + c * 8;
                mbar_expect_tx(fb, TILE_B);
                tma3d(tile0 + c * TILE_B, &tmap, 0, y0, zbase + c, fb);
            }
            int ps = DEPTH1 - 1, pph = 1;
            for (int c = DEPTH1 - 1; c < 64; ++c) {       // ch 4..63
                unsigned eb = mb0 + (DEPTH1 + ps) * 8;
                unsigned fb = mb0 + ps * 8;
                mbar_wait(eb, pph);
                mbar_expect_tx(fb, TILE_B);
                tma3d(tile0 + ps * TILE_B, &tmap, 0, y0, zbase + c, fb);
                if (++ps == DEPTH1) { ps = 0; pph ^= 1; }
            }
        }
    } else {
        // ---------- 8 consumer warps ----------
        u64t acc[8], bb[8];
        #pragma unroll
        for (int i = 0; i < 8; ++i) { acc[i] = 0ull; bb[i] = 0ull; }

        int cs = 0, cph = 0;
        for (int c = 0; c < 64; ++c) {
            mbar_wait(mb0 + cs * 8, cph);
            k1_compute(dynsm + cs * TILE_F, swp, c, tx, ty, acc, bb);
            __syncwarp();
            if (lane == 0) mbar_arrive(mb0 + (DEPTH1 + cs) * 8);
            if (++cs == DEPTH1) { cs = 0; cph ^= 1; }
        }

        // ---- boundary exchange (once): bb[o] = (bl -> left.hi, br -> right.lo)
        asm volatile("bar.sync 1, 256;" ::: "memory");    // all consumers done
        float2* sb = (float2*)dynsm;                       // reuse drained ring
        int sbase = (ty * 128 + tx) * 8;
        #pragma unroll
        for (int o = 0; o < 8; ++o) {
            F2U t; t.u = bb[o];
            sb[sbase + o] = t.f2;
        }
        asm volatile("bar.sync 1, 256;" ::: "memory");

        const float bbias = __ldg(b1);
        float s = 0.f, s2 = 0.f;
        size_t obase = (size_t)n * HW + (size_t)(rg * 16 + ty * 8) * Ww + 2 * tx;
        #pragma unroll
        for (int o = 0; o < 8; ++o) {
            float addlo = (tx > 0)   ? sb[sbase - 8 + o].y : 0.f;  // left's br
            float addhi = (tx < 127) ? sb[sbase + 8 + o].x : 0.f;  // right's bl
            float v0, v1;
            upk2(v0, v1, acc[o]);
            v0 += addlo + bbias;
            v1 += addhi + bbias;
            *(float2*)&g_h[obase + (size_t)o * Ww] = make_float2(v0, v1);
            s  += v0 + v1;
            s2 += v0 * v0 + v1 * v1;
        }
        #pragma unroll
        for (int off = 16; off; off >>= 1) {
            s  += __shfl_down_sync(0xffffffffu, s,  off);
            s2 += __shfl_down_sync(0xffffffffu, s2, off);
        }
        if (lane == 0) { red[tid >> 5] = s; red[8 + (tid >> 5)] = s2; }
    }
    __syncthreads();
    if (tid == 0) {
        float t = 0.f, t2 = 0.f;
        #pragma unroll
        for (int u = 0; u < 8; ++u) { t += red[u]; t2 += red[8 + u]; }
        int bid = n * 16 + rg;
        g_part1[bid * 2 + 0] = t;
        g_part1[bid * 2 + 1] = t2;
    }
}

// ================= K3': BN1 reduce (per block) + fuzzify + v/M Gram partials ====
// grid (32 rowgroups of 8, 16 n), 256 threads = one column each.
#define T3_ROWS 10
__global__ __launch_bounds__(256) void k3_fuzz(const float* __restrict__ g1,
                                               const float* __restrict__ be1,
                                               const float* __restrict__ lb,
                                               const float* __restrict__ ub) {
    __shared__ float sm[T3_ROWS][258];
    __shared__ float red54[8][54];
    __shared__ double dred[16];
    __shared__ float sAB[2];
    int tid = threadIdx.x;
    int rg = blockIdx.x, n = blockIdx.y;
    int wid = tid >> 5, lane = tid & 31;

    {
        float2 pa = *(const float2*)&g_part1[2 * tid];
        double s  = (double)pa.x;
        double s2 = (double)pa.y;
        #pragma unroll
        for (int off = 16; off; off >>= 1) {
            s  += __shfl_down_sync(0xffffffffu, s,  off);
            s2 += __shfl_down_sync(0xffffffffu, s2, off);
        }
        if (lane == 0) { dred[wid] = s; dred[8 + wid] = s2; }
    }
    for (int i = tid; i < T3_ROWS * 258; i += 256) (&sm[0][0])[i] = 0.f;
    __syncthreads();
    if (tid == 0) {
        double s = 0.0, s2 = 0.0;
        #pragma unroll
        for (int u = 0; u < 8; ++u) { s += dred[u]; s2 += dred[8 + u]; }
        double m   = s  / (double)NHW;
        double var = s2 / (double)NHW - m * m;
        double inv = 1.0 / sqrt(var + 1e-5);
        double A   = (double)g1[0] * inv;
        sAB[0] = (float)A;
        sAB[1] = (float)((double)be1[0] - m * A);
    }
    __syncthreads();
    const float A = sAB[0], B = sAB[1];

    float Ls[4], Us[4];
    #pragma unroll
    for (int f = 0; f < 4; ++f) { Ls[f] = __ldg(lb + f); Us[f] = __ldg(ub + f); }

    const float* hbase = g_h  + (size_t)n * HW;
    float*       fbase = g_fz + (size_t)n * HW;
    #pragma unroll
    for (int r = 0; r < T3_ROWS; ++r) {
        int gr = rg * 8 - 1 + r;
        if (gr >= 0 && gr < Hh) {
            float xv = hbase[gr * Ww + tid] * A + B;
            float fz = 0.f;
            #pragma unroll
            for (int f = 0; f < 4; ++f) {
                float lbv = Ls[f], ubv = Us[f];
                float ld = xv - lbv, ud = ubv - xv;
                bool inr  = (ld > 0.f) && (ud > 0.f);
                bool outr = (ld < 0.f) || (ud < 0.f);
                float e1 = __expf(-0.5f * ld * ld);
                float a2 = inr ? ud : (ud + 2.f * ld);
                float e2 = __expf(-0.5f * a2 * a2);
                fz += (inr || outr) ? (e1 + e2) : 0.f;
                if (outr) xv = 2.f * lbv - xv;
            }
            sm[r][tid + 1] = fz;
            if (r >= 1 && r <= 8) fbase[gr * Ww + tid] = fz;
        }
    }
    __syncthreads();

    float v[9], M[45];
    #pragma unroll
    for (int i = 0; i < 9; ++i) v[i] = 0.f;
    #pragma unroll
    for (int i = 0; i < 45; ++i) M[i] = 0.f;

    float f0 = sm[0][tid], f1 = sm[0][tid + 1], f2 = sm[0][tid + 2];
    float f3 = sm[1][tid], f4 = sm[1][tid + 1], f5 = sm[1][tid + 2];
    #pragma unroll
    for (int o = 0; o < 8; ++o) {
        float f6 = sm[o + 2][tid], f7 = sm[o + 2][tid + 1], f8 = sm[o + 2][tid + 2];
        float f[9] = {f0, f1, f2, f3, f4, f5, f6, f7, f8};
        int k = 0;
        #pragma unroll
        for (int i = 0; i < 9; ++i) {
            v[i] += f[i];
            #pragma unroll
            for (int j = i; j < 9; ++j) M[k++] = fmaf(f[i], f[j], M[k]);
        }
        f0 = f3; f1 = f4; f2 = f5;
        f3 = f6; f4 = f7; f5 = f8;
    }

    #pragma unroll
    for (int q = 0; q < 54; ++q) {
        float t = (q < 9) ? v[q] : M[q - 9];
        #pragma unroll
        for (int off = 16; off; off >>= 1) t += __shfl_down_sync(0xffffffffu, t, off);
        if (lane == 0) red54[wid][q] = t;
    }
    __syncthreads();
    if (tid < 54) {
        float t = 0.f;
        #pragma unroll
        for (int u = 0; u < 8; ++u) t += red54[u][tid];
        g_part2[(n * 32 + rg) * 54 + tid] = t;
    }
}

// ================= K4b: reduce partials + per-channel BN2 fuse ==================
__global__ __launch_bounds__(512) void k4b_fuse(const float* __restrict__ w2,
                                                const float* __restrict__ b2,
                                                const float* __restrict__ g2,
                                                const float* __restrict__ be2) {
    __shared__ float redA[8][54];
    __shared__ double S[54];
    int tid = threadIdx.x;
    if (tid < 432) {
        int chunk = tid / 54, q = tid % 54;
        float t = 0.f;
        #pragma unroll 8
        for (int b = chunk * 64; b < chunk * 64 + 64; ++b)
            t += g_part2[b * 54 + q];
        redA[chunk][q] = t;
    }
    __syncthreads();
    if (tid < 54) {
        double t = 0.0;
        #pragma unroll
        for (int u = 0; u < 8; ++u) t += (double)redA[u][tid];
        S[tid] = t;
    }
    __syncthreads();
    if (tid < 64) {
        int c = tid;
        double w[9];
        #pragma unroll
        for (int j = 0; j < 9; ++j) w[j] = (double)w2[c * 9 + j];
        double bb = (double)b2[c];
        double dot = 0.0;
        #pragma unroll
        for (int j = 0; j < 9; ++j) dot += w[j] * S[j];
        double S2 = 0.0;
        int k = 9;
        #pragma unroll
        for (int i = 0; i < 9; ++i)
            #pragma unroll
            for (int j = i; j < 9; ++j) {
                double m = S[k++];
                S2 += (i == j) ? w[i] * w[i] * m : 2.0 * w[i] * w[j] * m;
            }
        double S1   = dot + bb * (double)NHW;
        double sq   = S2 + 2.0 * bb * dot + bb * bb * (double)NHW;
        double mean = S1 / (double)NHW;
        double var  = sq / (double)NHW - mean * mean;
        double inv  = 1.0 / sqrt(var + 1e-5);
        double Af   = (double)g2[c] * inv;
        double Bf   = (double)be2[c] - mean * Af;
        #pragma unroll
        for (int j = 0; j < 9; ++j) g_Wf[c * 10 + j] = (float)(w[j] * Af);
        g_Wf[c * 10 + 9] = (float)(bb * Af + Bf);
    }
}

// ================= K5: conv2 (1ch -> 64ch) + fused BN2, write output ============
__global__ __launch_bounds__(256) void k5_conv2(float* __restrict__ out) {
    __shared__ u64t swf[640];
    int tid = threadIdx.x;
    int rg = blockIdx.x, n = blockIdx.y;
    int c0 = blockIdx.z * 32;
    for (int i = tid; i < 640; i += 256) { float w = g_Wf[i]; swf[i] = pk2(w, w); }
    __syncthreads();

    int wt = tid & 63, ht = tid >> 6;
    int wq = wt * 4, gr0 = rg * 8 + ht * 2;
    const float* base = g_fz + (size_t)n * HW;

    u64t p[4][5];
    #pragma unroll
    for (int rr = 0; rr < 4; ++rr) {
        int gr = gr0 - 1 + rr;
        bool rok = (gr >= 0 && gr < Hh);
        float wv[6];
        #pragma unroll
        for (int cc = 0; cc < 6; ++cc) {
            int gc = wq - 1 + cc;
            bool ok = rok && (gc >= 0) && (gc < Ww);
            wv[cc] = ok ? __ldg(base + gr * Ww + gc) : 0.f;
        }
        #pragma unroll
        for (int cc = 0; cc < 5; ++cc) p[rr][cc] = pk2(wv[cc], wv[cc + 1]);
    }

    size_t obase = (size_t)n * Cc * HW + (size_t)gr0 * Ww + wq;
    for (int c = c0; c < c0 + 32; ++c) {
        u64t wp[9];
        #pragma unroll
        for (int j = 0; j < 9; ++j) wp[j] = swf[c * 10 + j];
        u64t bp = swf[c * 10 + 9];
        #pragma unroll
        for (int a = 0; a < 2; ++a) {
            u64t y01 = bp, y23 = bp;
            #pragma unroll
            for (int kh = 0; kh < 3; ++kh) {
                int row = a + kh;
                #pragma unroll
                for (int kw = 0; kw < 3; ++kw) {
                    fma2(y01, wp[kh * 3 + kw], p[row][kw]);
                    fma2(y23, wp[kh * 3 + kw], p[row][kw + 2]);
                }
            }
            float y0, y1, y2, y3;
            upk2(y0, y1, y01);
            upk2(y2, y3, y23);
            __stcs((float4*)(out + obase + (size_t)c * HW + (size_t)a * Ww),
                   make_float4(y0, y1, y2, y3));
        }
    }
}

// ================= launch =======================================================
typedef CUresult (*PFN_tmEnc)(CUtensorMap*, CUtensorMapDataType, cuuint32_t, void*,
                              const cuuint64_t*, const cuuint64_t*, const cuuint32_t*,
                              const cuuint32_t*, CUtensorMapInterleave, CUtensorMapSwizzle,
                              CUtensorMapL2promotion, CUtensorMapFloatOOBfill);

extern "C" void kernel_launch(void* const* d_in, const int* in_sizes, int n_in,
                              void* d_out, int out_size) {
    const float* x   = (const float*)d_in[0];
    const float* w1  = (const float*)d_in[1];
    const float* b1  = (const float*)d_in[2];
    const float* w2  = (const float*)d_in[3];
    const float* b2  = (const float*)d_in[4];
    const float* g1  = (const float*)d_in[5];
    const float* be1 = (const float*)d_in[6];
    const float* g2  = (const float*)d_in[7];
    const float* be2 = (const float*)d_in[8];
    const float* lb  = (const float*)d_in[9];
    const float* ub  = (const float*)d_in[10];
    float* out = (float*)d_out;

    static PFN_tmEnc tmEnc = nullptr;
    if (!tmEnc) {
        void* fn = nullptr;
        cudaDriverEntryPointQueryResult st;
        cudaGetDriverEntryPoint("cuTensorMapEncodeTiled", &fn, cudaEnableDefault, &st);
        tmEnc = (PFN_tmEnc)fn;
    }

    CUtensorMap tmap;
    {
        cuuint64_t dims[3]    = {256, 256, (cuuint64_t)(Cc * Nn)};
        cuuint64_t strides[2] = {256 * 4, (cuuint64_t)HW * 4};
        cuuint32_t box[3]     = {256, 18, 1};
        cuuint32_t es[3]      = {1, 1, 1};
        tmEnc(&tmap, CU_TENSOR_MAP_DATA_TYPE_FLOAT32, 3, (void*)x,
              dims, strides, box, es,
              CU_TENSOR_MAP_INTERLEAVE_NONE, CU_TENSOR_MAP_SWIZZLE_NONE,
              CU_TENSOR_MAP_L2_PROMOTION_L2_128B, CU_TENSOR_MAP_FLOAT_OOB_FILL_NONE);
    }

    static bool attr_set = false;
    const int k1_smem = DEPTH1 * TILE_B;   // 92160
    if (!attr_set) {
        cudaFuncSetAttribute(k1_conv1, cudaFuncAttributeMaxDynamicSharedMemorySize, k1_smem);
        attr_set = true;
    }

    k1_conv1<<<dim3(16, 16), 288, k1_smem>>>(tmap, w1, b1);
    k3_fuzz<<<dim3(32, 16), 256>>>(g1, be1, lb, ub);
    k4b_fuse<<<1, 512>>>(w2, b2, g2, be2);
    k5_conv2<<<dim3(32, 16, 2), 256>>>(out);
}

// round 16
// speedup vs baseline: 1.0215x; 1.0040x over previous
#include <cuda.h>
#include <cuda_runtime.h>

#define Nn 16
#define Cc 64
#define Hh 256
#define Ww 256
#define HW 65536
#define NHW 1048576

// ---------------- scratch ----------------
__device__ float g_h[NHW];          // conv1 output (1 channel)
__device__ float g_fz[NHW];         // fuzzify output
__device__ float g_part1[256 * 2];  // K1 partials (sum, sumsq) per tile
__device__ float g_part2[256 * 54]; // Gram partials (v[9], M[45]) per tile
__device__ float g_Wf[64 * 10];     // fused conv2 weights (9) + bias (1)
__device__ int   g_flag;            // grid barrier counter (memset per launch)

// ---------------- helpers ----------------
__device__ __forceinline__ unsigned smem_u32(const void* p) {
    unsigned r;
    asm("{ .reg .u64 t; cvta.to.shared.u64 t, %1; cvt.u32.u64 %0, t; }" : "=r"(r) : "l"(p));
    return r;
}
typedef unsigned long long u64t;
union F2U { float2 f2; u64t u; };
__device__ __forceinline__ u64t pk2(float lo, float hi) {
    u64t r;
    asm("mov.b64 %0, {%1, %2};" : "=l"(r) : "f"(lo), "f"(hi));
    return r;
}
__device__ __forceinline__ void fma2(u64t& d, u64t a, u64t b) {
    asm("fma.rn.f32x2 %0, %1, %2, %0;" : "+l"(d) : "l"(a), "l"(b));
}
__device__ __forceinline__ void upk2(float& lo, float& hi, u64t v) {
    asm("mov.b64 {%0, %1}, %2;" : "=f"(lo), "=f"(hi) : "l"(v));
}
// ---- mbarrier / TMA ----
__device__ __forceinline__ void mbar_init(unsigned a, unsigned cnt) {
    asm volatile("mbarrier.init.shared.b64 [%0], %1;" :: "r"(a), "r"(cnt) : "memory");
}
__device__ __forceinline__ void mbar_expect_tx(unsigned a, unsigned bytes) {
    asm volatile("mbarrier.arrive.expect_tx.shared.b64 _, [%0], %1;" :: "r"(a), "r"(bytes) : "memory");
}
__device__ __forceinline__ void mbar_arrive(unsigned a) {
    asm volatile("mbarrier.arrive.shared.b64 _, [%0];" :: "r"(a) : "memory");
}
__device__ __forceinline__ void mbar_wait(unsigned a, unsigned phase) {
    asm volatile(
        "{\n\t.reg .pred P;\n\t"
        "WL_%=:\n\t"
        "mbarrier.try_wait.parity.acquire.cta.shared::cta.b64 P, [%0], %1, 0x989680;\n\t"
        "@P bra.uni WD_%=;\n\t"
        "bra.uni WL_%=;\n\t"
        "WD_%=:\n\t}"
        :: "r"(a), "r"(phase) : "memory");
}
__device__ __forceinline__ void tma3d(unsigned dst, const CUtensorMap* map,
                                      int cx, int cy, int cz, unsigned mbar) {
    asm volatile(
        "cp.async.bulk.tensor.3d.shared::cta.global.tile.mbarrier::complete_tx::bytes "
        "[%0], [%1, {%2, %3, %4}], [%5];"
        :: "r"(dst), "l"(map), "r"(cx), "r"(cy), "r"(cz), "r"(mbar) : "memory");
}

// ================= K1': conv1 (TMA ring) + grid barrier + BN1 + fuzzify + Gram ==
// grid (16 rowgroups of 16, 16 n) = 256 blocks, 2 resident/SM (enforced).
// 288 threads: 8 consumer warps + 1 TMA producer warp.
#define DEPTH1 5
#define TILE_F (18 * 256)           // floats per tile
#define TILE_B (TILE_F * 4)         // 18432 bytes
#define NTILES 256

// weight table per channel/kh: [0]=(w1,w0) [1]=(w2,w1) [2]=(w2,w0)
__device__ __forceinline__ void k1_compute(const float* tilef, const u64t* swp,
                                           int c, int tx, int ty,
                                           u64t acc[8], u64t bb[8]) {
    u64t wp[9];
    #pragma unroll
    for (int j = 0; j < 9; ++j) wp[j] = swp[c * 9 + j];
    #pragma unroll
    for (int rr = 0; rr < 10; ++rr) {
        const float* row = tilef + (ty * 8 + rr) * 256;
        F2U v2; v2.u = *(const u64t*)&row[2 * tx];
        u64t pf0 = pk2(v2.f2.x, v2.f2.x);
        u64t pf1 = pk2(v2.f2.y, v2.f2.y);
        #pragma unroll
        for (int kh = 0; kh < 3; ++kh) {
            int o = rr - kh;
            if (o >= 0 && o < 8) {
                fma2(acc[o], wp[kh * 3 + 0], pf0);
                fma2(acc[o], wp[kh * 3 + 1], pf1);
                fma2(bb[o],  wp[kh * 3 + 2], v2.u);
            }
        }
    }
}

__global__ __launch_bounds__(288, 2) void k1_conv1(const __grid_constant__ CUtensorMap tmap,
                                                   const float* __restrict__ w1,
                                                   const float* __restrict__ b1,
                                                   const float* __restrict__ g1,
                                                   const float* __restrict__ be1,
                                                   const float* __restrict__ lb,
                                                   const float* __restrict__ ub) {
    extern __shared__ __align__(128) float dynsm[];  // DEPTH1 * TILE_F floats
    __shared__ u64t swp[576];
    __shared__ float red[16];
    __shared__ float red54[8][54];
    __shared__ double dred[16];
    __shared__ float sAB[2];
    __shared__ __align__(8) u64t mbar[2 * DEPTH1];   // full[0..4], empty[0..4]

    const int tid = threadIdx.x;
    const int rg = blockIdx.x, n = blockIdx.y;
    const int tx = tid & 127, ty = (tid >> 7) & 1;
    const int lane = tid & 31;
    const unsigned mb0 = smem_u32(&mbar[0]);
    const unsigned tile0 = smem_u32(&dynsm[0]);

    // weight table: per (c,kh): (w1,w0), (w2,w1), (w2,w0)
    for (int i = tid; i < 576; i += 288) {
        int base = (i / 3) * 3;
        int j = i % 3;
        float wa  = w1[base + ((j == 0) ? 1 : 2)];
        float wbv = w1[base + ((j == 1) ? 1 : 0)];
        swp[i] = pk2(wa, wbv);
    }
    if (tid == 0) {
        #pragma unroll
        for (int s = 0; s < DEPTH1; ++s) {
            mbar_init(mb0 + s * 8, 1);
            mbar_init(mb0 + (DEPTH1 + s) * 8, 8);
        }
    }
    __syncthreads();

    const int zbase = n * Cc;
    const int y0 = rg * 16 - 1;

    // ===================== Phase A: conv1 =====================
    if (tid >= 256) {
        if (tid == 256) {
            #pragma unroll
            for (int c = 0; c < DEPTH1 - 1; ++c) {
                unsigned fb = mb0 + c * 8;
                mbar_expect_tx(fb, TILE_B);
                tma3d(tile0 + c * TILE_B, &tmap, 0, y0, zbase + c, fb);
            }
            int ps = DEPTH1 - 1, pph = 1;
            for (int c = DEPTH1 - 1; c < 64; ++c) {
                unsigned eb = mb0 + (DEPTH1 + ps) * 8;
                unsigned fb = mb0 + ps * 8;
                mbar_wait(eb, pph);
                mbar_expect_tx(fb, TILE_B);
                tma3d(tile0 + ps * TILE_B, &tmap, 0, y0, zbase + c, fb);
                if (++ps == DEPTH1) { ps = 0; pph ^= 1; }
            }
        }
    } else {
        u64t acc[8], bb[8];
        #pragma unroll
        for (int i = 0; i < 8; ++i) { acc[i] = 0ull; bb[i] = 0ull; }

        int cs = 0, cph = 0;
        for (int c = 0; c < 64; ++c) {
            mbar_wait(mb0 + cs * 8, cph);
            k1_compute(dynsm + cs * TILE_F, swp, c, tx, ty, acc, bb);
            __syncwarp();
            if (lane == 0) mbar_arrive(mb0 + (DEPTH1 + cs) * 8);
            if (++cs == DEPTH1) { cs = 0; cph ^= 1; }
        }

        // boundary exchange through drained ring
        asm volatile("bar.sync 1, 256;" ::: "memory");
        float2* sb = (float2*)dynsm;
        int sbase = (ty * 128 + tx) * 8;
        #pragma unroll
        for (int o = 0; o < 8; ++o) {
            F2U t; t.u = bb[o];
            sb[sbase + o] = t.f2;
        }
        asm volatile("bar.sync 1, 256;" ::: "memory");

        const float bbias = __ldg(b1);
        float s = 0.f, s2 = 0.f;
        size_t obase = (size_t)n * HW + (size_t)(rg * 16 + ty * 8) * Ww + 2 * tx;
        #pragma unroll
        for (int o = 0; o < 8; ++o) {
            float addlo = (tx > 0)   ? sb[sbase - 8 + o].y : 0.f;
            float addhi = (tx < 127) ? sb[sbase + 8 + o].x : 0.f;
            float v0, v1;
            upk2(v0, v1, acc[o]);
            v0 += addlo + bbias;
            v1 += addhi + bbias;
            *(float2*)&g_h[obase + (size_t)o * Ww] = make_float2(v0, v1);
            s  += v0 + v1;
            s2 += v0 * v0 + v1 * v1;
        }
        #pragma unroll
        for (int off = 16; off; off >>= 1) {
            s  += __shfl_down_sync(0xffffffffu, s,  off);
            s2 += __shfl_down_sync(0xffffffffu, s2, off);
        }
        if (lane == 0) { red[tid >> 5] = s; red[8 + (tid >> 5)] = s2; }
    }
    __syncthreads();
    if (tid == 0) {
        float t = 0.f, t2 = 0.f;
        #pragma unroll
        for (int u = 0; u < 8; ++u) { t += red[u]; t2 += red[8 + u]; }
        int bid = n * 16 + rg;
        g_part1[bid * 2 + 0] = t;
        g_part1[bid * 2 + 1] = t2;
    }

    // ===================== grid-wide barrier =====================
    __threadfence();                 // each thread: publish its g_h stores
    __syncthreads();
    if (tid == 0) {
        atomicAdd(&g_flag, 1);
        while (true) {
            int v;
            asm volatile("ld.global.acquire.gpu.b32 %0, [%1];" : "=r"(v) : "l"(&g_flag));
            if (v >= NTILES) break;
            __nanosleep(64);
        }
    }
    __syncthreads();
    __threadfence();

    // ===================== Phase B: BN1 + fuzzify + Gram =====================
    float (*smf)[258] = (float (*)[258])dynsm;   // 18 x 258 floats (ring drained)
    for (int i = tid; i < 18 * 258; i += 288) (&smf[0][0])[i] = 0.f;

    if (tid < 256) {
        float2 pa = *(const float2*)&g_part1[2 * tid];
        double ds  = (double)pa.x;
        double ds2 = (double)pa.y;
        #pragma unroll
        for (int off = 16; off; off >>= 1) {
            ds  += __shfl_down_sync(0xffffffffu, ds,  off);
            ds2 += __shfl_down_sync(0xffffffffu, ds2, off);
        }
        if (lane == 0) { dred[tid >> 5] = ds; dred[8 + (tid >> 5)] = ds2; }
    }
    __syncthreads();
    if (tid == 0) {
        double s = 0.0, s2 = 0.0;
        #pragma unroll
        for (int u = 0; u < 8; ++u) { s += dred[u]; s2 += dred[8 + u]; }
        double m   = s  / (double)NHW;
        double var = s2 / (double)NHW - m * m;
        double inv = 1.0 / sqrt(var + 1e-5);
        double A   = (double)g1[0] * inv;
        sAB[0] = (float)A;
        sAB[1] = (float)((double)be1[0] - m * A);
    }
    __syncthreads();

    if (tid < 256) {
        const float A = sAB[0], B = sAB[1];
        float Ls[4], Us[4];
        #pragma unroll
        for (int f = 0; f < 4; ++f) { Ls[f] = __ldg(lb + f); Us[f] = __ldg(ub + f); }

        const float* hbase = g_h  + (size_t)n * HW;
        float*       fbase = g_fz + (size_t)n * HW;
        #pragma unroll
        for (int r = 0; r < 18; ++r) {
            int gr = rg * 16 - 1 + r;
            if (gr >= 0 && gr < Hh) {
                float xv = hbase[gr * Ww + tid] * A + B;
                float fz = 0.f;
                #pragma unroll
                for (int f = 0; f < 4; ++f) {
                    float lbv = Ls[f], ubv = Us[f];
                    float ld = xv - lbv, ud = ubv - xv;
                    bool inr  = (ld > 0.f) && (ud > 0.f);
                    bool outr = (ld < 0.f) || (ud < 0.f);
                    float e1 = __expf(-0.5f * ld * ld);
                    float a2 = inr ? ud : (ud + 2.f * ld);
                    float e2 = __expf(-0.5f * a2 * a2);
                    fz += (inr || outr) ? (e1 + e2) : 0.f;
                    if (outr) xv = 2.f * lbv - xv;
                }
                smf[r][tid + 1] = fz;
                if (r >= 1 && r <= 16) fbase[gr * Ww + tid] = fz;
            }
        }
    }
    __syncthreads();

    if (tid < 256) {
        float v[9], M[45];
        #pragma unroll
        for (int i = 0; i < 9; ++i) v[i] = 0.f;
        #pragma unroll
        for (int i = 0; i < 45; ++i) M[i] = 0.f;

        float f0 = smf[0][tid], f1 = smf[0][tid + 1], f2 = smf[0][tid + 2];
        float f3 = smf[1][tid], f4 = smf[1][tid + 1], f5 = smf[1][tid + 2];
        #pragma unroll
        for (int o = 0; o < 16; ++o) {
            float f6 = smf[o + 2][tid], f7 = smf[o + 2][tid + 1], f8 = smf[o + 2][tid + 2];
            float f[9] = {f0, f1, f2, f3, f4, f5, f6, f7, f8};
            int k = 0;
            #pragma unroll
            for (int i = 0; i < 9; ++i) {
                v[i] += f[i];
                #pragma unroll
                for (int j = i; j < 9; ++j) M[k++] = fmaf(f[i], f[j], M[k]);
            }
            f0 = f3; f1 = f4; f2 = f5;
            f3 = f6; f4 = f7; f5 = f8;
        }

        #pragma unroll
        for (int q = 0; q < 54; ++q) {
            float t = (q < 9) ? v[q] : M[q - 9];
            #pragma unroll
            for (int off = 16; off; off >>= 1) t += __shfl_down_sync(0xffffffffu, t, off);
            if (lane == 0) red54[tid >> 5][q] = t;
        }
    }
    __syncthreads();
    if (tid < 54) {
        float t = 0.f;
        #pragma unroll
        for (int u = 0; u < 8; ++u) t += red54[u][tid];
        g_part2[(n * 16 + rg) * 54 + tid] = t;
    }
}

// ================= K4b: reduce partials + per-channel BN2 fuse ==================
__global__ __launch_bounds__(512) void k4b_fuse(const float* __restrict__ w2,
                                                const float* __restrict__ b2,
                                                const float* __restrict__ g2,
                                                const float* __restrict__ be2) {
    __shared__ float redA[8][54];
    __shared__ double S[54];
    int tid = threadIdx.x;
    if (tid < 432) {
        int chunk = tid / 54, q = tid % 54;
        float t = 0.f;
        #pragma unroll 8
        for (int b = chunk * 32; b < chunk * 32 + 32; ++b)
            t += g_part2[b * 54 + q];
        redA[chunk][q] = t;
    }
    __syncthreads();
    if (tid < 54) {
        double t = 0.0;
        #pragma unroll
        for (int u = 0; u < 8; ++u) t += (double)redA[u][tid];
        S[tid] = t;
    }
    __syncthreads();
    if (tid < 64) {
        int c = tid;
        double w[9];
        #pragma unroll
        for (int j = 0; j < 9; ++j) w[j] = (double)w2[c * 9 + j];
        double bb = (double)b2[c];
        double dot = 0.0;
        #pragma unroll
        for (int j = 0; j < 9; ++j) dot += w[j] * S[j];
        double S2 = 0.0;
        int k = 9;
        #pragma unroll
        for (int i = 0; i < 9; ++i)
            #pragma unroll
            for (int j = i; j < 9; ++j) {
                double m = S[k++];
                S2 += (i == j) ? w[i] * w[i] * m : 2.0 * w[i] * w[j] * m;
            }
        double S1   = dot + bb * (double)NHW;
        double sq   = S2 + 2.0 * bb * dot + bb * bb * (double)NHW;
        double mean = S1 / (double)NHW;
        double var  = sq / (double)NHW - mean * mean;
        double inv  = 1.0 / sqrt(var + 1e-5);
        double Af   = (double)g2[c] * inv;
        double Bf   = (double)be2[c] - mean * Af;
        #pragma unroll
        for (int j = 0; j < 9; ++j) g_Wf[c * 10 + j] = (float)(w[j] * Af);
        g_Wf[c * 10 + 9] = (float)(bb * Af + Bf);
    }
}

// ================= K5: conv2 (1ch -> 64ch) + fused BN2, write output ============
__global__ __launch_bounds__(256) void k5_conv2(float* __restrict__ out) {
    __shared__ u64t swf[640];
    int tid = threadIdx.x;
    int rg = blockIdx.x, n = blockIdx.y;
    int c0 = blockIdx.z * 32;
    for (int i = tid; i < 640; i += 256) { float w = g_Wf[i]; swf[i] = pk2(w, w); }
    __syncthreads();

    int wt = tid & 63, ht = tid >> 6;
    int wq = wt * 4, gr0 = rg * 8 + ht * 2;
    const float* base = g_fz + (size_t)n * HW;

    u64t p[4][5];
    #pragma unroll
    for (int rr = 0; rr < 4; ++rr) {
        int gr = gr0 - 1 + rr;
        bool rok = (gr >= 0 && gr < Hh);
        float wv[6];
        #pragma unroll
        for (int cc = 0; cc < 6; ++cc) {
            int gc = wq - 1 + cc;
            bool ok = rok && (gc >= 0) && (gc < Ww);
            wv[cc] = ok ? __ldg(base + gr * Ww + gc) : 0.f;
        }
        #pragma unroll
        for (int cc = 0; cc < 5; ++cc) p[rr][cc] = pk2(wv[cc], wv[cc + 1]);
    }

    size_t obase = (size_t)n * Cc * HW + (size_t)gr0 * Ww + wq;
    for (int c = c0; c < c0 + 32; ++c) {
        u64t wp[9];
        #pragma unroll
        for (int j = 0; j < 9; ++j) wp[j] = swf[c * 10 + j];
        u64t bp = swf[c * 10 + 9];
        #pragma unroll
        for (int a = 0; a < 2; ++a) {
            u64t y01 = bp, y23 = bp;
            #pragma unroll
            for (int kh = 0; kh < 3; ++kh) {
                int row = a + kh;
                #pragma unroll
                for (int kw = 0; kw < 3; ++kw) {
                    fma2(y01, wp[kh * 3 + kw], p[row][kw]);
                    fma2(y23, wp[kh * 3 + kw], p[row][kw + 2]);
                }
            }
            float y0, y1, y2, y3;
            upk2(y0, y1, y01);
            upk2(y2, y3, y23);
            __stcs((float4*)(out + obase + (size_t)c * HW + (size_t)a * Ww),
                   make_float4(y0, y1, y2, y3));
        }
    }
}

// ================= launch =======================================================
typedef CUresult (*PFN_tmEnc)(CUtensorMap*, CUtensorMapDataType, cuuint32_t, void*,
                              const cuuint64_t*, const cuuint64_t*, const cuuint32_t*,
                              const cuuint32_t*, CUtensorMapInterleave, CUtensorMapSwizzle,
                              CUtensorMapL2promotion, CUtensorMapFloatOOBfill);

extern "C" void kernel_launch(void* const* d_in, const int* in_sizes, int n_in,
                              void* d_out, int out_size) {
    const float* x   = (const float*)d_in[0];
    const float* w1  = (const float*)d_in[1];
    const float* b1  = (const float*)d_in[2];
    const float* w2  = (const float*)d_in[3];
    const float* b2  = (const float*)d_in[4];
    const float* g1  = (const float*)d_in[5];
    const float* be1 = (const float*)d_in[6];
    const float* g2  = (const float*)d_in[7];
    const float* be2 = (const float*)d_in[8];
    const float* lb  = (const float*)d_in[9];
    const float* ub  = (const float*)d_in[10];
    float* out = (float*)d_out;

    static PFN_tmEnc tmEnc = nullptr;
    static void* flag_addr = nullptr;
    if (!tmEnc) {
        void* fn = nullptr;
        cudaDriverEntryPointQueryResult st;
        cudaGetDriverEntryPoint("cuTensorMapEncodeTiled", &fn, cudaEnableDefault, &st);
        tmEnc = (PFN_tmEnc)fn;
        cudaGetSymbolAddress(&flag_addr, g_flag);
    }

    CUtensorMap tmap;
    {
        cuuint64_t dims[3]    = {256, 256, (cuuint64_t)(Cc * Nn)};
        cuuint64_t strides[2] = {256 * 4, (cuuint64_t)HW * 4};
        cuuint32_t box[3]     = {256, 18, 1};
        cuuint32_t es[3]      = {1, 1, 1};
        tmEnc(&tmap, CU_TENSOR_MAP_DATA_TYPE_FLOAT32, 3, (void*)x,
              dims, strides, box, es,
              CU_TENSOR_MAP_INTERLEAVE_NONE, CU_TENSOR_MAP_SWIZZLE_NONE,
              CU_TENSOR_MAP_L2_PROMOTION_L2_128B, CU_TENSOR_MAP_FLOAT_OOB_FILL_NONE);
    }

    static bool attr_set = false;
    const int k1_smem = DEPTH1 * TILE_B;   // 92160
    if (!attr_set) {
        cudaFuncSetAttribute(k1_conv1, cudaFuncAttributeMaxDynamicSharedMemorySize, k1_smem);
        attr_set = true;
    }

    cudaMemsetAsync(flag_addr, 0, sizeof(int));
    k1_conv1<<<dim3(16, 16), 288, k1_smem>>>(tmap, w1, b1, g1, be1, lb, ub);
    k4b_fuse<<<1, 512>>>(w2, b2, g2, be2);
    k5_conv2<<<dim3(32, 16, 2), 256>>>(out);
}